// round 5
// baseline (speedup 1.0000x reference)
#include <cuda_runtime.h>
#include <math_constants.h>

#define B_ 8
#define N_ 2048
#define C_ 64
#define K_ 32
#define W_COLS 67   // C + 3
#define FULL 0xffffffffu

// Scratch (allocation-free rule: device globals)
__device__ __align__(16) float g_Gt[B_*N_*C_];   // (b, n, o): inv[o] * (W_f @ feats)[o,n]
__device__ int g_idx[B_*N_*K_];

// ---------------------------------------------------------------------------
// Fused kernel AB: blocks [0,128) = Gt precompute (kA), blocks [128,1152) = kNN.
// kB distance REPLICATES the reference cdist rounding exactly:
//   sq  = ((x*x + y*y) + z*z)           (plain mul/add)
//   dot = fma(z,z', fma(y,y', x*x'))    (ascending fma chain)
//   d2  = max((sq_i + sq_j) - 2*dot, 0) (2*dot exact => fma(-2,dot,sum) == sub)
// Selection: top-32 by (d2, idx) lexicographic (matches stable top_k).
// ---------------------------------------------------------------------------
#define KA_BLOCKS 128
__global__ __launch_bounds__(512) void kAB(const float* __restrict__ coords,
                                           const float* __restrict__ feats,
                                           const float* __restrict__ conv_w,
                                           const float* __restrict__ gamma,
                                           const float* __restrict__ var) {
    __shared__ __align__(16) float sbuf[12288];   // 48 KB
    int bid = blockIdx.x;
    int t = threadIdx.x;

    if (bid < KA_BLOCKS) {
        // ---------------- kA path
        float (*sW)[C_]  = (float(*)[C_])sbuf;            // [c][o] 16KB
        float (*sF)[128] = (float(*)[128])(sbuf + 4096);  // [c][n] 32KB
        int b  = bid >> 4;
        int n0 = (bid & 15) * 128;

        for (int x = t; x < C_*C_; x += 512) {
            int o = x & 63, c = x >> 6;
            float inv = gamma[o] * rsqrtf(var[o] + 1e-5f);
            sW[c][o] = conv_w[o*W_COLS + 3 + c] * inv;
        }
        for (int x = t; x < C_*128; x += 512) {
            int c = x >> 7, n = x & 127;
            sF[c][n] = feats[(b*C_ + c)*N_ + n0 + n];
        }
        __syncthreads();

        int oT = (t & 15) * 4;
        int nT = (t >> 4) * 4;
        float acc[4][4] = {};
        #pragma unroll 8
        for (int c = 0; c < C_; c++) {
            float w0 = sW[c][oT+0], w1 = sW[c][oT+1], w2 = sW[c][oT+2], w3 = sW[c][oT+3];
            #pragma unroll
            for (int j = 0; j < 4; j++) {
                float f = sF[c][nT+j];
                acc[j][0] = fmaf(w0, f, acc[j][0]);
                acc[j][1] = fmaf(w1, f, acc[j][1]);
                acc[j][2] = fmaf(w2, f, acc[j][2]);
                acc[j][3] = fmaf(w3, f, acc[j][3]);
            }
        }
        #pragma unroll
        for (int j = 0; j < 4; j++) {
            float4 v = make_float4(acc[j][0], acc[j][1], acc[j][2], acc[j][3]);
            *reinterpret_cast<float4*>(&g_Gt[((b*N_) + n0 + nT + j)*C_ + oT]) = v;
        }
        return;
    }

    // ---------------- kB path: exact kNN (K=32), warp-per-query
    {
        float4* sC = (float4*)sbuf;    // 32KB: coords + precomputed sq in .w
        int kb = bid - KA_BLOCKS;
        int warp = t >> 5, lane = t & 31;
        int b = kb >> 7;                        // 128 blocks per batch
        int i = ((kb & 127) << 4) + warp;       // query index

        for (int x = t; x < N_; x += 512) {
            const float* c = coords + (b*N_ + x)*3;
            float cx = c[0], cy = c[1], cz = c[2];
            float sq = __fadd_rn(__fadd_rn(__fmul_rn(cx,cx), __fmul_rn(cy,cy)),
                                 __fmul_rn(cz,cz));
            sC[x] = make_float4(cx, cy, cz, sq);
        }
        __syncthreads();

        float4 q = sC[i];

        auto refd2 = [&](const float4& p) -> float {
            float dot = __fmaf_rn(q.z, p.z, __fmaf_rn(q.y, p.y, __fmul_rn(q.x, p.x)));
            // 2*dot exact => single-rounded fma == reference's mul-then-sub
            float d2  = __fmaf_rn(-2.0f, dot, __fadd_rn(q.w, p.w));
            return fmaxf(d2, 0.0f);
        };

        // ---- Pass 1: provable upper bound md0 on the 32nd smallest d2.
        // Each lane takes min over its disjoint 64-candidate hand; every lane
        // then owns >=1 element <= max-of-minima => >=32 elements <= md0.
        float lmin = CUDART_INF_F;
        #pragma unroll 4
        for (int it = 0; it < N_/32; it++)
            lmin = fminf(lmin, refd2(sC[it*32 + lane]));
        float md0 = lmin;
        #pragma unroll
        for (int off = 16; off; off >>= 1)
            md0 = fmaxf(md0, __shfl_xor_sync(FULL, md0, off));

        // ---- Init: first 32 candidates, bitonic-sorted ascending by (d2, idx)
        float bd = refd2(sC[lane]);
        int   bi = lane;
        #pragma unroll
        for (int k = 2; k <= 32; k <<= 1) {
            #pragma unroll
            for (int j = k >> 1; j > 0; j >>= 1) {
                float od = __shfl_xor_sync(FULL, bd, j);
                int   oi = __shfl_xor_sync(FULL, bi, j);
                bool up       = ((lane & k) == 0);
                bool keep_min = (((lane & j) == 0) == up);
                bool less     = (od < bd) || (od == bd && oi < bi);
                bool take     = keep_min ? less : !less;   // pairs unique
                if (take) { bd = od; bi = oi; }
            }
        }

        // ---- Pass 2: filtered scan + sorted-lane insertion.
        // Invariant: (bd,bi) sorted ascending across lanes; worst in lane 31.
        for (int tt = 32; tt < N_; tt += 32) {
            int jj = tt + lane;
            float d2 = refd2(sC[jj]);
            unsigned m = __ballot_sync(FULL, d2 <= md0);
            while (m) {    // warp-uniform serial insertion
                int src = __ffs(m) - 1;
                m &= m - 1;
                float cd = __shfl_sync(FULL, d2, src);
                int   cj = tt + src;
                // does the candidate beat the current worst (lane 31)?
                bool gt_self = (bd > cd) || (bd == cd && bi > cj);
                if (__ballot_sync(FULL, gt_self) & 0x80000000u) {
                    float p_bd = __shfl_up_sync(FULL, bd, 1);
                    int   p_bi = __shfl_up_sync(FULL, bi, 1);
                    bool gt_prev = (lane > 0) &&
                                   ((p_bd > cd) || (p_bd == cd && p_bi > cj));
                    if (gt_self) {
                        bd = gt_prev ? p_bd : cd;
                        bi = gt_prev ? p_bi : cj;
                    }
                }
            }
        }
        g_idx[(b*N_ + i)*K_ + lane] = bi;
    }
}

// ---------------------------------------------------------------------------
// Kernel C: per point (warp-per-point):
//   rel_k = (coords[idx_k] - coords[i]) / R
//   density: 16th-smallest pairwise dist among the 32 grouped points,
//            via two in-register bitonic sort16 + lower-half pairing:
//            kth = max_i min(a[i], b[15-i])   (exact multiset identity)
//   out[o,i] = sum_k w_k * relu(Gt[idx_k][o] + Wrel'[o]·rel_k + bias'[o])
// ---------------------------------------------------------------------------
__global__ __launch_bounds__(256) void kC(const float* __restrict__ coords,
                                          const float* __restrict__ conv_w,
                                          const float* __restrict__ gamma,
                                          const float* __restrict__ beta,
                                          const float* __restrict__ mean,
                                          const float* __restrict__ var,
                                          float* __restrict__ out) {
    __shared__ __align__(16) float4 sRel[8][K_];   // (rx,ry,rz,w) per neighbor
    __shared__ int sJn[8][K_];
    int t = threadIdx.x;
    int warp = t >> 5, lane = t & 31;
    int pidx = blockIdx.x * 8 + warp;
    int b = pidx >> 11;
    int i = pidx & (N_ - 1);

    // per-lane channel constants (o0 = lane, o1 = lane + 32), BN folded
    int o0 = lane, o1 = lane + 32;
    float inv0 = gamma[o0] * rsqrtf(var[o0] + 1e-5f);
    float inv1 = gamma[o1] * rsqrtf(var[o1] + 1e-5f);
    float w0x = conv_w[o0*W_COLS+0]*inv0, w0y = conv_w[o0*W_COLS+1]*inv0, w0z = conv_w[o0*W_COLS+2]*inv0;
    float w1x = conv_w[o1*W_COLS+0]*inv1, w1y = conv_w[o1*W_COLS+1]*inv1, w1z = conv_w[o1*W_COLS+2]*inv1;
    float bb0 = beta[o0] - mean[o0]*inv0;
    float bb1 = beta[o1] - mean[o1]*inv1;

    // lane's neighbor -> rel coords, staged to smem
    int jk = g_idx[pidx*K_ + lane];
    const float* qc = coords + (b*N_ + i)*3;
    float qx = qc[0], qy = qc[1], qz = qc[2];
    const float* gc = coords + (b*N_ + jk)*3;
    float rx = (gc[0] - qx) / 0.2f;
    float ry = (gc[1] - qy) / 0.2f;
    float rz = (gc[2] - qz) / 0.2f;
    sRel[warp][lane] = make_float4(rx, ry, rz, 0.f);
    sJn[warp][lane] = jk;
    __syncwarp();

    // all 32 pairwise d2 from this lane's point (diagonal -> +inf)
    float v[K_];
    #pragma unroll
    for (int j = 0; j < K_; j++) {
        float4 o = sRel[warp][j];                 // LDS.128 broadcast
        float dx = o.x - rx, dy = o.y - ry, dz = o.z - rz;
        float d = dx*dx + dy*dy + dz*dz;
        v[j] = (j == lane) ? CUDART_INF_F : d;
    }
    // bitonic sort16 ascending on v[0..15] and v[16..31]
    #pragma unroll
    for (int h = 0; h < 2; h++) {
        const int base = h * 16;
        #pragma unroll
        for (int k = 2; k <= 16; k <<= 1) {
            #pragma unroll
            for (int j = k >> 1; j > 0; j >>= 1) {
                #pragma unroll
                for (int ii = 0; ii < 16; ii++) {
                    int ll = ii ^ j;
                    if (ll > ii) {
                        float a = v[base+ii], c = v[base+ll];
                        float lo = fminf(a, c), hi = fmaxf(a, c);
                        if ((ii & k) == 0) { v[base+ii] = lo; v[base+ll] = hi; }
                        else               { v[base+ii] = hi; v[base+ll] = lo; }
                    }
                }
            }
        }
    }
    // 16th smallest of the union = max_i min(a[i], b[15-i])
    float kd = fminf(v[0], v[31]);
    #pragma unroll
    for (int ii = 1; ii < 16; ii++)
        kd = fmaxf(kd, fminf(v[ii], v[31-ii]));

    float kth = sqrtf(kd) * 0.2f;                 // back to absolute units
    float raw = fmaxf(kth, 1e-8f);
    raw = raw * raw * raw;
    float sum = raw;
    #pragma unroll
    for (int off = 16; off; off >>= 1) sum += __shfl_xor_sync(FULL, sum, off);
    float w = raw / fmaxf(sum, 1e-8f);
    sRel[warp][lane].w = w;
    __syncwarp();

    // weighted accumulation over 32 neighbors; coalesced Gt gathers
    const float* Gb = g_Gt + (b*N_)*C_;
    float acc0 = 0.f, acc1 = 0.f;
    #pragma unroll 4
    for (int k = 0; k < K_; k++) {
        float4 r4 = sRel[warp][k];                // LDS.128 broadcast
        int    jn = sJn[warp][k];
        float g0 = Gb[jn*C_ + o0];
        float g1 = Gb[jn*C_ + o1];
        float v0 = fmaf(w0z, r4.z, fmaf(w0y, r4.y, fmaf(w0x, r4.x, g0 + bb0)));
        float v1 = fmaf(w1z, r4.z, fmaf(w1y, r4.y, fmaf(w1x, r4.x, g1 + bb1)));
        v0 = fmaxf(v0, 0.f);
        v1 = fmaxf(v1, 0.f);
        acc0 = fmaf(r4.w, v0, acc0);
        acc1 = fmaf(r4.w, v1, acc1);
    }
    out[(b*C_ + o0)*N_ + i] = acc0;
    out[(b*C_ + o1)*N_ + i] = acc1;
}

extern "C" void kernel_launch(void* const* d_in, const int* in_sizes, int n_in,
                              void* d_out, int out_size) {
    const float* coords = (const float*)d_in[0];
    const float* feats  = (const float*)d_in[1];
    const float* conv_w = (const float*)d_in[2];
    const float* gamma  = (const float*)d_in[3];
    const float* beta   = (const float*)d_in[4];
    const float* mean   = (const float*)d_in[5];
    const float* var    = (const float*)d_in[6];
    float* out = (float*)d_out;

    kAB<<<KA_BLOCKS + B_*N_/16, 512>>>(coords, feats, conv_w, gamma, var);
    kC<<<B_*N_/8, 256>>>(coords, conv_w, gamma, beta, mean, var, out);
}

// round 6
// speedup vs baseline: 1.0178x; 1.0178x over previous
#include <cuda_runtime.h>
#include <math_constants.h>

#define B_ 8
#define N_ 2048
#define C_ 64
#define K_ 32
#define W_COLS 67   // C + 3
#define FULL 0xffffffffu

// Scratch (allocation-free rule: device globals)
__device__ __align__(16) float g_Gt[B_*N_*C_];     // (b, n, o)
__device__ int g_idx[B_*N_*K_];
__device__ __align__(16) float4 g_relw[B_*N_*K_];  // (rx, ry, rz, w) per neighbor

// ---------------------------------------------------------------------------
// Fused kernel AB: blocks [0,128) = Gt precompute, blocks [128,1152) = kNN
// + rel/density-weight computation (absorbed into kB's idle ALU slots).
// kB distance REPLICATES the reference cdist rounding exactly:
//   sq  = ((x*x + y*y) + z*z)           (plain mul/add)
//   dot = fma(z,z', fma(y,y', x*x'))    (ascending fma chain)
//   d2  = max((sq_i + sq_j) - 2*dot, 0) (2*dot exact => fused fma == sub)
// Selection: top-32 by (d2, idx) lexicographic (matches stable top_k).
// ---------------------------------------------------------------------------
#define KA_BLOCKS 128
__global__ __launch_bounds__(512, 2) void kAB(const float* __restrict__ coords,
                                              const float* __restrict__ feats,
                                              const float* __restrict__ conv_w,
                                              const float* __restrict__ gamma,
                                              const float* __restrict__ var) {
    __shared__ __align__(16) float sbuf[12288];   // 48 KB
    int bid = blockIdx.x;
    int t = threadIdx.x;

    if (bid < KA_BLOCKS) {
        // ---------------- kA path
        float (*sW)[C_]  = (float(*)[C_])sbuf;            // [c][o] 16KB
        float (*sF)[128] = (float(*)[128])(sbuf + 4096);  // [c][n] 32KB
        int b  = bid >> 4;
        int n0 = (bid & 15) * 128;

        for (int x = t; x < C_*C_; x += 512) {
            int o = x & 63, c = x >> 6;
            float inv = gamma[o] * rsqrtf(var[o] + 1e-5f);
            sW[c][o] = conv_w[o*W_COLS + 3 + c] * inv;
        }
        for (int x = t; x < C_*128; x += 512) {
            int c = x >> 7, n = x & 127;
            sF[c][n] = feats[(b*C_ + c)*N_ + n0 + n];
        }
        __syncthreads();

        int oT = (t & 15) * 4;
        int nT = (t >> 4) * 4;
        float acc[4][4] = {};
        #pragma unroll 8
        for (int c = 0; c < C_; c++) {
            float w0 = sW[c][oT+0], w1 = sW[c][oT+1], w2 = sW[c][oT+2], w3 = sW[c][oT+3];
            #pragma unroll
            for (int j = 0; j < 4; j++) {
                float f = sF[c][nT+j];
                acc[j][0] = fmaf(w0, f, acc[j][0]);
                acc[j][1] = fmaf(w1, f, acc[j][1]);
                acc[j][2] = fmaf(w2, f, acc[j][2]);
                acc[j][3] = fmaf(w3, f, acc[j][3]);
            }
        }
        #pragma unroll
        for (int j = 0; j < 4; j++) {
            float4 v4 = make_float4(acc[j][0], acc[j][1], acc[j][2], acc[j][3]);
            *reinterpret_cast<float4*>(&g_Gt[((b*N_) + n0 + nT + j)*C_ + oT]) = v4;
        }
        return;
    }

    // ---------------- kB path: exact kNN (K=32) + rel + density, warp/query
    {
        float4* sC = (float4*)sbuf;                     // 32KB coords (+sq in .w)
        float4 (*sRel)[K_] = (float4(*)[K_])(sbuf + 8192);  // 16 warps x 32 x 16B = 8KB
        int kb = bid - KA_BLOCKS;
        int warp = t >> 5, lane = t & 31;
        int b = kb >> 7;                        // 128 blocks per batch
        int i = ((kb & 127) << 4) + warp;       // query index

        for (int x = t; x < N_; x += 512) {
            const float* c = coords + (b*N_ + x)*3;
            float cx = c[0], cy = c[1], cz = c[2];
            float sq = __fadd_rn(__fadd_rn(__fmul_rn(cx,cx), __fmul_rn(cy,cy)),
                                 __fmul_rn(cz,cz));
            sC[x] = make_float4(cx, cy, cz, sq);
        }
        __syncthreads();

        float4 q = sC[i];

        auto refd2 = [&](const float4& p) -> float {
            float dot = __fmaf_rn(q.z, p.z, __fmaf_rn(q.y, p.y, __fmul_rn(q.x, p.x)));
            float d2  = __fmaf_rn(-2.0f, dot, __fadd_rn(q.w, p.w));
            return fmaxf(d2, 0.0f);
        };

        // ---- Pass 1: provable upper bound md0 on the 32nd smallest d2
        float lmin = CUDART_INF_F;
        #pragma unroll 4
        for (int it = 0; it < N_/32; it++)
            lmin = fminf(lmin, refd2(sC[it*32 + lane]));
        float md0 = lmin;
        #pragma unroll
        for (int off = 16; off; off >>= 1)
            md0 = fmaxf(md0, __shfl_xor_sync(FULL, md0, off));

        // ---- Init: first 32 candidates, bitonic-sorted ascending by (d2, idx)
        float bd = refd2(sC[lane]);
        int   bi = lane;
        #pragma unroll
        for (int k = 2; k <= 32; k <<= 1) {
            #pragma unroll
            for (int j = k >> 1; j > 0; j >>= 1) {
                float od = __shfl_xor_sync(FULL, bd, j);
                int   oi = __shfl_xor_sync(FULL, bi, j);
                bool up       = ((lane & k) == 0);
                bool keep_min = (((lane & j) == 0) == up);
                bool less     = (od < bd) || (od == bd && oi < bi);
                bool take     = keep_min ? less : !less;   // pairs unique
                if (take) { bd = od; bi = oi; }
            }
        }
        float md = __shfl_sync(FULL, bd, 31);   // current worst of set
        int   mi = __shfl_sync(FULL, bi, 31);

        // ---- Pass 2: filtered scan + sorted-lane insertion (R3 scheme)
        for (int tt = 32; tt < N_; tt += 32) {
            int jj = tt + lane;
            float d2 = refd2(sC[jj]);
            bool beat = (d2 <= md0) &&
                        ((d2 < md) || (d2 == md && jj < mi));
            unsigned m = __ballot_sync(FULL, beat);
            while (m) {    // warp-uniform serial insertion
                int src = __ffs(m) - 1;
                m &= m - 1;
                float cd = __shfl_sync(FULL, d2, src);
                int   cj = tt + src;
                if (!((cd < md) || (cd == md && cj < mi))) continue;  // stale

                float p_bd = __shfl_up_sync(FULL, bd, 1);
                int   p_bi = __shfl_up_sync(FULL, bi, 1);
                bool gt_self = (bd > cd) || (bd == cd && bi > cj);
                bool gt_prev = (lane > 0) &&
                               ((p_bd > cd) || (p_bd == cd && p_bi > cj));
                if (gt_self) {
                    bd = gt_prev ? p_bd : cd;
                    bi = gt_prev ? p_bi : cj;
                }
                md = __shfl_sync(FULL, bd, 31);
                mi = __shfl_sync(FULL, bi, 31);
            }
        }

        // ---- Tail: rel coords + density weight (absorbed ALU work)
        float4 pb = sC[bi];
        float rx = (pb.x - q.x) / 0.2f;
        float ry = (pb.y - q.y) / 0.2f;
        float rz = (pb.z - q.z) / 0.2f;
        sRel[warp][lane] = make_float4(rx, ry, rz, 0.f);
        __syncwarp();

        // all 32 pairwise d2 from this lane's neighbor (diagonal -> +inf)
        float v[K_];
        #pragma unroll
        for (int j = 0; j < K_; j++) {
            float4 o = sRel[warp][j];             // LDS.128 broadcast
            float dx = o.x - rx, dy = o.y - ry, dz = o.z - rz;
            float d = dx*dx + dy*dy + dz*dz;
            v[j] = (j == lane) ? CUDART_INF_F : d;
        }
        // bitonic sort16 ascending on v[0..15] and v[16..31]
        #pragma unroll
        for (int h = 0; h < 2; h++) {
            const int base = h * 16;
            #pragma unroll
            for (int k = 2; k <= 16; k <<= 1) {
                #pragma unroll
                for (int j = k >> 1; j > 0; j >>= 1) {
                    #pragma unroll
                    for (int ii = 0; ii < 16; ii++) {
                        int ll = ii ^ j;
                        if (ll > ii) {
                            float a = v[base+ii], c = v[base+ll];
                            float lo = fminf(a, c), hi = fmaxf(a, c);
                            if ((ii & k) == 0) { v[base+ii] = lo; v[base+ll] = hi; }
                            else               { v[base+ii] = hi; v[base+ll] = lo; }
                        }
                    }
                }
            }
        }
        // 16th smallest of the union = max_i min(a[i], b[15-i])
        float kd = fminf(v[0], v[31]);
        #pragma unroll
        for (int ii = 1; ii < 16; ii++)
            kd = fmaxf(kd, fminf(v[ii], v[31-ii]));

        float kth = sqrtf(kd) * 0.2f;             // back to absolute units
        float raw = fmaxf(kth, 1e-8f);
        raw = raw * raw * raw;
        float sum = raw;
        #pragma unroll
        for (int off = 16; off; off >>= 1) sum += __shfl_xor_sync(FULL, sum, off);
        float w = raw / fmaxf(sum, 1e-8f);

        int gi = (b*N_ + i)*K_ + lane;
        g_relw[gi] = make_float4(rx, ry, rz, w);
        g_idx[gi] = bi;
    }
}

// ---------------------------------------------------------------------------
// Kernel C (slim): per point (warp-per-point), pure gather + FMA:
//   out[o,i] = sum_k w_k * relu(Gt[idx_k][o] + Wrel'[o]·rel_k + bias'[o])
// ---------------------------------------------------------------------------
__global__ __launch_bounds__(256) void kC(const float* __restrict__ conv_w,
                                          const float* __restrict__ gamma,
                                          const float* __restrict__ beta,
                                          const float* __restrict__ mean,
                                          const float* __restrict__ var,
                                          float* __restrict__ out) {
    __shared__ __align__(16) float4 sRel[8][K_];   // (rx,ry,rz,w) per neighbor
    __shared__ int sJn[8][K_];
    int t = threadIdx.x;
    int warp = t >> 5, lane = t & 31;
    int pidx = blockIdx.x * 8 + warp;
    int b = pidx >> 11;
    int i = pidx & (N_ - 1);

    // per-lane channel constants (o0 = lane, o1 = lane + 32), BN folded
    int o0 = lane, o1 = lane + 32;
    float inv0 = gamma[o0] * rsqrtf(var[o0] + 1e-5f);
    float inv1 = gamma[o1] * rsqrtf(var[o1] + 1e-5f);
    float w0x = conv_w[o0*W_COLS+0]*inv0, w0y = conv_w[o0*W_COLS+1]*inv0, w0z = conv_w[o0*W_COLS+2]*inv0;
    float w1x = conv_w[o1*W_COLS+0]*inv1, w1y = conv_w[o1*W_COLS+1]*inv1, w1z = conv_w[o1*W_COLS+2]*inv1;
    float bb0 = beta[o0] - mean[o0]*inv0;
    float bb1 = beta[o1] - mean[o1]*inv1;

    // stage this point's 32 neighbors (rel + w + idx) into smem
    sRel[warp][lane] = g_relw[pidx*K_ + lane];
    sJn[warp][lane]  = g_idx[pidx*K_ + lane];
    __syncwarp();

    // weighted accumulation over 32 neighbors; coalesced Gt gathers
    const float* Gb = g_Gt + (b*N_)*C_;
    float acc0 = 0.f, acc1 = 0.f;
    #pragma unroll 4
    for (int k = 0; k < K_; k++) {
        float4 r4 = sRel[warp][k];                // LDS.128 broadcast
        int    jn = sJn[warp][k];
        float g0 = Gb[jn*C_ + o0];
        float g1 = Gb[jn*C_ + o1];
        float v0 = fmaf(w0z, r4.z, fmaf(w0y, r4.y, fmaf(w0x, r4.x, g0 + bb0)));
        float v1 = fmaf(w1z, r4.z, fmaf(w1y, r4.y, fmaf(w1x, r4.x, g1 + bb1)));
        v0 = fmaxf(v0, 0.f);
        v1 = fmaxf(v1, 0.f);
        acc0 = fmaf(r4.w, v0, acc0);
        acc1 = fmaf(r4.w, v1, acc1);
    }
    out[(b*C_ + o0)*N_ + i] = acc0;
    out[(b*C_ + o1)*N_ + i] = acc1;
}

extern "C" void kernel_launch(void* const* d_in, const int* in_sizes, int n_in,
                              void* d_out, int out_size) {
    const float* coords = (const float*)d_in[0];
    const float* feats  = (const float*)d_in[1];
    const float* conv_w = (const float*)d_in[2];
    const float* gamma  = (const float*)d_in[3];
    const float* beta   = (const float*)d_in[4];
    const float* mean   = (const float*)d_in[5];
    const float* var    = (const float*)d_in[6];
    float* out = (float*)d_out;

    kAB<<<KA_BLOCKS + B_*N_/16, 512>>>(coords, feats, conv_w, gamma, var);
    kC<<<B_*N_/8, 256>>>(conv_w, gamma, beta, mean, var, out);
}